// round 8
// baseline (speedup 1.0000x reference)
#include <cuda_runtime.h>

#define NQ 4
#define QDIM 16
#define BB 4
#define SS 512
#define EE 512
#define NROWS (BB*SS)
#define QKV_ROWS_PER_BLK 4
#define QKV_BLKS (NROWS / QKV_ROWS_PER_BLK)

// Scratch (no allocations allowed). g_q/g_k store tanh(tanh-projection).
__device__ __align__(16) float g_q[NROWS * 4];
__device__ __align__(16) float g_k[NROWS * 4];
__device__ __align__(16) float g_v[NROWS * 4];
__device__ float g_C[81];

struct c2 { float x, y; };
__device__ __forceinline__ c2 cmul(c2 a, c2 b) { return {a.x*b.x - a.y*b.y, a.x*b.y + a.y*b.x}; }
__device__ __forceinline__ c2 cadd(c2 a, c2 b) { return {a.x + b.x, a.y + b.y}; }

// ---- packed f32x2 helpers (FFMA2/FADD2/FMUL2: PTX-only) ----
typedef unsigned long long u64c;
__device__ __forceinline__ u64c pk2(float lo, float hi) {
    u64c r; asm("mov.b64 %0, {%1, %2};" : "=l"(r) : "f"(lo), "f"(hi)); return r;
}
__device__ __forceinline__ u64c pkc(float v) { return pk2(v, v); }
__device__ __forceinline__ void upk2(u64c v, float& lo, float& hi) {
    asm("mov.b64 {%0, %1}, %2;" : "=f"(lo), "=f"(hi) : "l"(v));
}
__device__ __forceinline__ u64c fma2(u64c a, u64c b, u64c c) {
    u64c d; asm("fma.rn.f32x2 %0, %1, %2, %3;" : "=l"(d) : "l"(a), "l"(b), "l"(c)); return d;
}
__device__ __forceinline__ u64c mul2(u64c a, u64c b) {
    u64c d; asm("mul.rn.f32x2 %0, %1, %2;" : "=l"(d) : "l"(a), "l"(b)); return d;
}
__device__ __forceinline__ u64c add2(u64c a, u64c b) {
    u64c d; asm("add.rn.f32x2 %0, %1, %2;" : "=l"(d) : "l"(a), "l"(b)); return d;
}
__device__ __forceinline__ float frcp(float x) {
    float r; asm("rcp.approx.f32 %0, %1;" : "=f"(r) : "f"(x)); return r;
}

// tanh(q + k) from tq = tanh(q), tk = tanh(k):  (tq+tk)/(1+tq*tk), packed.
__device__ __forceinline__ u64c tanh_sum2(u64c tq, u64c tk, u64c ONE) {
    u64c num = add2(tq, tk);
    u64c den = fma2(tq, tk, ONE);
    float d0, d1; upk2(den, d0, d1);
    return mul2(num, pk2(frcp(d0), frcp(d1)));
}

// Packed Taylor sin/cos, |a| < 0.965: err < 2e-8.
__device__ __forceinline__ void sincos2p(u64c a, u64c& s, u64c& c, u64c ONE) {
    u64c a2 = mul2(a, a);
    u64c h = fma2(a2, pkc(2.7557319e-6f), pkc(-1.9841270e-4f));
    h = fma2(a2, h, pkc(8.3333333e-3f));
    h = fma2(a2, h, pkc(-1.6666667e-1f));
    h = fma2(a2, h, ONE);
    s = mul2(a, h);
    u64c g = fma2(a2, pkc(-2.7557319e-7f), pkc(2.4801587e-5f));
    g = fma2(a2, g, pkc(-1.3888889e-3f));
    g = fma2(a2, g, pkc(4.1666667e-2f));
    g = fma2(a2, g, pkc(-0.5f));
    c = fma2(a2, g, ONE);
}

// Accurate tanh for the cold qkv path.
__device__ __forceinline__ float ftanh(float x) {
    float e2 = __expf(2.0f * x);
    return __fdividef(e2 - 1.0f, e2 + 1.0f);
}

// ---------------------------------------------------------------------------
// Setup body (128 threads): build U, A = Re(U^H Z U), collapse to 81-coeff C.
// Wire w <-> bit position (3 - w). Fast MUFU trig (gate angles ~0.05).
// ---------------------------------------------------------------------------
__device__ void setup_body(const float* __restrict__ qw, int tid) {
    __shared__ c2 G[8][4];
    __shared__ c2 U[QDIM][QDIM];
    __shared__ float A[QDIM][QDIM];

    if (tid < 8) {
        float a = qw[tid * 3 + 0] * 0.5f;
        float b = qw[tid * 3 + 1] * 0.5f;
        float c = qw[tid * 3 + 2] * 0.5f;
        float ca, sa, cb, sb, zc, zs;
        __sincosf(a, &sa, &ca);
        __sincosf(b, &sb, &cb);
        __sincosf(c, &zs, &zc);
        c2 X00 = {ca, 0.f}, X01 = {0.f, -sa}, X10 = {0.f, -sa}, X11 = {ca, 0.f};
        c2 M00 = {cb * X00.x - sb * X10.x, cb * X00.y - sb * X10.y};
        c2 M01 = {cb * X01.x - sb * X11.x, cb * X01.y - sb * X11.y};
        c2 M10 = {sb * X00.x + cb * X10.x, sb * X00.y + cb * X10.y};
        c2 M11 = {sb * X01.x + cb * X11.x, sb * X01.y + cb * X11.y};
        c2 e0 = {zc, -zs}, e1 = {zc, zs};
        G[tid][0] = cmul(e0, M00); G[tid][1] = cmul(e0, M01);
        G[tid][2] = cmul(e1, M10); G[tid][3] = cmul(e1, M11);
    }
    __syncthreads();

    if (tid < QDIM) {
        c2 amp[QDIM];
        #pragma unroll
        for (int d = 0; d < QDIM; d++) amp[d] = {0.f, 0.f};
        amp[tid] = {1.f, 0.f};
        #pragma unroll
        for (int layer = 0; layer < 2; layer++) {
            #pragma unroll
            for (int w = 0; w < 4; w++) {
                c2 g00 = G[layer * 4 + w][0], g01 = G[layer * 4 + w][1];
                c2 g10 = G[layer * 4 + w][2], g11 = G[layer * 4 + w][3];
                int mask = 1 << (3 - w);
                #pragma unroll
                for (int d = 0; d < QDIM; d++) {
                    if (d & mask) continue;
                    c2 x0 = amp[d], x1 = amp[d | mask];
                    amp[d]        = cadd(cmul(g00, x0), cmul(g01, x1));
                    amp[d | mask] = cadd(cmul(g10, x0), cmul(g11, x1));
                }
            }
            const int cm[4] = {8, 4, 2, 1};
            const int tm[4] = {4, 2, 1, 8};
            #pragma unroll
            for (int p = 0; p < 4; p++) {
                #pragma unroll
                for (int d = 0; d < QDIM; d++) {
                    if ((d & cm[p]) && !(d & tm[p])) {
                        c2 t = amp[d];
                        amp[d] = amp[d | tm[p]];
                        amp[d | tm[p]] = t;
                    }
                }
            }
        }
        #pragma unroll
        for (int m = 0; m < QDIM; m++) U[m][tid] = amp[m];
    }
    __syncthreads();

    #pragma unroll
    for (int it = 0; it < 2; it++) {
        int idx = tid + it * 128;
        int d = idx >> 4, e = idx & 15;
        float s = 0.f;
        #pragma unroll
        for (int m = 0; m < QDIM; m++) {
            float z = 4.0f - 2.0f * (float)__popc(m);
            s += z * (U[m][d].x * U[m][e].x + U[m][d].y * U[m][e].y);
        }
        A[d][e] = s;
    }
    __syncthreads();

    if (tid < 81) {
        int t0 = tid / 27, t1 = (tid / 9) % 3, t2 = (tid / 3) % 3, t3 = tid % 3;
        int tw[4] = {t0, t1, t2, t3};
        int xmask = 0, m1 = 0;
        #pragma unroll
        for (int w = 0; w < 4; w++) {
            if (tw[w] == 2) xmask |= 1 << (3 - w);
            if (tw[w] == 1) m1   |= 1 << (3 - w);
        }
        float s = 0.f;
        #pragma unroll
        for (int d = 0; d < QDIM; d++) {
            float sgn = (__popc(d & m1) & 1) ? -1.0f : 1.0f;
            s += sgn * A[d][d ^ xmask];
        }
        g_C[tid] = s * 0.0625f;
    }
}

// ---------------------------------------------------------------------------
// Merged setup + QKV. Block 0: setup. Blocks 1..QKV_BLKS handle 4 rows each.
// Thread t owns e = 4t..4t+3; W rows for those e held in registers across
// all 4 rows (cuts W L2 traffic 4x vs one-row blocks).
// Stores tq = tanh(tanh(xWq+bq)), tk = tanh(tanh(xWk+bk)), v = xWv+bv.
// ---------------------------------------------------------------------------
__global__ void __launch_bounds__(128) qkv_setup_kernel(
        const float* __restrict__ x,
        const float* __restrict__ Wq, const float* __restrict__ bq,
        const float* __restrict__ Wk, const float* __restrict__ bk,
        const float* __restrict__ Wv, const float* __restrict__ bv,
        const float* __restrict__ qw) {
    int tid = threadIdx.x;  // 128
    if (blockIdx.x == 0) { setup_body(qw, tid); return; }

    int row0 = (blockIdx.x - 1) * QKV_ROWS_PER_BLK;
    int wid = tid >> 5, lane = tid & 31;

    // W rows for e = 4t..4t+3, loaded once.
    const float4* wqp = (const float4*)Wq + 4 * tid;
    const float4* wkp = (const float4*)Wk + 4 * tid;
    const float4* wvp = (const float4*)Wv + 4 * tid;
    float4 q0 = __ldg(wqp), q1 = __ldg(wqp + 1), q2 = __ldg(wqp + 2), q3 = __ldg(wqp + 3);
    float4 k0 = __ldg(wkp), k1 = __ldg(wkp + 1), k2 = __ldg(wkp + 2), k3 = __ldg(wkp + 3);
    float4 v0 = __ldg(wvp), v1 = __ldg(wvp + 1), v2 = __ldg(wvp + 2), v3 = __ldg(wvp + 3);

    __shared__ float wr[4][12];

    for (int rr = 0; rr < QKV_ROWS_PER_BLK; rr++) {
        int row = row0 + rr;
        float4 xv = __ldg((const float4*)(x + row * EE) + tid);

        float acc[12];
        acc[0] = xv.x*q0.x + xv.y*q1.x + xv.z*q2.x + xv.w*q3.x;
        acc[1] = xv.x*q0.y + xv.y*q1.y + xv.z*q2.y + xv.w*q3.y;
        acc[2] = xv.x*q0.z + xv.y*q1.z + xv.z*q2.z + xv.w*q3.z;
        acc[3] = xv.x*q0.w + xv.y*q1.w + xv.z*q2.w + xv.w*q3.w;
        acc[4] = xv.x*k0.x + xv.y*k1.x + xv.z*k2.x + xv.w*k3.x;
        acc[5] = xv.x*k0.y + xv.y*k1.y + xv.z*k2.y + xv.w*k3.y;
        acc[6] = xv.x*k0.z + xv.y*k1.z + xv.z*k2.z + xv.w*k3.z;
        acc[7] = xv.x*k0.w + xv.y*k1.w + xv.z*k2.w + xv.w*k3.w;
        acc[8]  = xv.x*v0.x + xv.y*v1.x + xv.z*v2.x + xv.w*v3.x;
        acc[9]  = xv.x*v0.y + xv.y*v1.y + xv.z*v2.y + xv.w*v3.y;
        acc[10] = xv.x*v0.z + xv.y*v1.z + xv.z*v2.z + xv.w*v3.z;
        acc[11] = xv.x*v0.w + xv.y*v1.w + xv.z*v2.w + xv.w*v3.w;

        #pragma unroll
        for (int i = 0; i < 12; i++) {
            #pragma unroll
            for (int o = 16; o > 0; o >>= 1)
                acc[i] += __shfl_xor_sync(0xffffffffu, acc[i], o);
        }
        if (lane == 0) {
            #pragma unroll
            for (int i = 0; i < 12; i++) wr[wid][i] = acc[i];
        }
        __syncthreads();
        if (tid < 12) {
            float s = wr[0][tid] + wr[1][tid] + wr[2][tid] + wr[3][tid];
            if (tid < 4) {
                g_q[row * 4 + tid] = ftanh(ftanh(s + bq[tid]));
            } else if (tid < 8) {
                g_k[row * 4 + (tid - 4)] = ftanh(ftanh(s + bk[tid - 4]));
            } else {
                g_v[row * 4 + (tid - 8)] = s + bv[tid - 8];
            }
        }
        __syncthreads();  // before wr reuse next row
    }
}

// ---------------------------------------------------------------------------
// Fused scores + softmax + attended + output. One block (128 thr) per (b,i).
// Thread t owns j = {t, t+128, t+256, t+384}: two packed FFMA2 chains sharing
// every coefficient LDS.64 (duplicated float2 — operand-format-matched, no
// repacking MOVs).
// ---------------------------------------------------------------------------
__global__ void __launch_bounds__(128, 8) attn_kernel(
        float* __restrict__ out, float* __restrict__ attn,
        const float* __restrict__ Wout, const float* __restrict__ bout) {
    int row = blockIdx.x;
    int tid = threadIdx.x;  // 128
    int b = row / SS;
    int wid = tid >> 5, lane = tid & 31;

    __shared__ __align__(8) float2 Csh2[81];
    __shared__ float qsh[4];
    __shared__ float rm[4];
    __shared__ float rs[4];
    __shared__ float wsum[4][4];
    __shared__ float att4[4];

    if (tid < 81) { float c = g_C[tid]; Csh2[tid] = make_float2(c, c); }
    if (tid < 4)  qsh[tid] = g_q[row * 4 + tid];

    const float4* kp = (const float4*)(g_k + (b * SS + tid) * 4);
    float4 kk0 = __ldg(kp);        // j = tid
    float4 kk1 = __ldg(kp + 128);  // j = tid+128
    float4 kk2 = __ldg(kp + 256);
    float4 kk3 = __ldg(kp + 384);
    __syncthreads();

    const u64c ONE = pkc(1.0f);
    u64c tq0 = pkc(qsh[0]), tq1 = pkc(qsh[1]), tq2 = pkc(qsh[2]), tq3 = pkc(qsh[3]);

    // chain A = (j, j+128), chain B = (j+256, j+384)
    u64c a0A = tanh_sum2(tq0, pk2(kk0.x, kk1.x), ONE);
    u64c a1A = tanh_sum2(tq1, pk2(kk0.y, kk1.y), ONE);
    u64c a2A = tanh_sum2(tq2, pk2(kk0.z, kk1.z), ONE);
    u64c a3A = tanh_sum2(tq3, pk2(kk0.w, kk1.w), ONE);
    u64c a0B = tanh_sum2(tq0, pk2(kk2.x, kk3.x), ONE);
    u64c a1B = tanh_sum2(tq1, pk2(kk2.y, kk3.y), ONE);
    u64c a2B = tanh_sum2(tq2, pk2(kk2.z, kk3.z), ONE);
    u64c a3B = tanh_sum2(tq3, pk2(kk2.w, kk3.w), ONE);

    u64c c0A, s0A, c1A, s1A, c2A, s2A, c3A, s3A;
    u64c c0B, s0B, c1B, s1B, c2B, s2B, c3B, s3B;
    sincos2p(a0A, s0A, c0A, ONE); sincos2p(a1A, s1A, c1A, ONE);
    sincos2p(a2A, s2A, c2A, ONE); sincos2p(a3A, s3A, c3A, ONE);
    sincos2p(a0B, s0B, c0B, ONE); sincos2p(a1B, s1B, c1B, ONE);
    sincos2p(a2B, s2B, c2B, ONE); sincos2p(a3B, s3B, c3B, ONE);

    // contraction: both chains share each coefficient LDS.64.
    const u64c* Cd = (const u64c*)Csh2;
    u64c B0A[3], B0B[3];
    #pragma unroll
    for (int t0 = 0; t0 < 3; t0++) {
        u64c B1A[3], B1B[3];
        #pragma unroll
        for (int t1 = 0; t1 < 3; t1++) {
            int base = (t0 * 3 + t1) * 9;
            u64c C0 = Cd[base + 0], C1 = Cd[base + 1], C2 = Cd[base + 2];
            u64c C3 = Cd[base + 3], C4 = Cd[base + 4], C5 = Cd[base + 5];
            u64c C6 = Cd[base + 6], C7 = Cd[base + 7], C8 = Cd[base + 8];
            u64c A20 = fma2(C2, s3A, fma2(C1, c3A, C0));
            u64c A21 = fma2(C5, s3A, fma2(C4, c3A, C3));
            u64c A22 = fma2(C8, s3A, fma2(C7, c3A, C6));
            B1A[t1] = fma2(A22, s2A, fma2(A21, c2A, A20));
            u64c D20 = fma2(C2, s3B, fma2(C1, c3B, C0));
            u64c D21 = fma2(C5, s3B, fma2(C4, c3B, C3));
            u64c D22 = fma2(C8, s3B, fma2(C7, c3B, C6));
            B1B[t1] = fma2(D22, s2B, fma2(D21, c2B, D20));
        }
        B0A[t0] = fma2(B1A[2], s1A, fma2(B1A[1], c1A, B1A[0]));
        B0B[t0] = fma2(B1B[2], s1B, fma2(B1B[1], c1B, B1B[0]));
    }
    u64c totA = fma2(B0A[2], s0A, fma2(B0A[1], c0A, B0A[0]));
    u64c totB = fma2(B0B[2], s0B, fma2(B0B[1], c0B, B0B[0]));

    float sc0, sc1, sc2, sc3;
    upk2(totA, sc0, sc1);
    upk2(totB, sc2, sc3);
    sc0 *= 0.5f; sc1 *= 0.5f; sc2 *= 0.5f; sc3 *= 0.5f;  // /sqrt(NQ)

    // --- softmax ---
    float m = fmaxf(fmaxf(sc0, sc1), fmaxf(sc2, sc3));
    #pragma unroll
    for (int o = 16; o > 0; o >>= 1) m = fmaxf(m, __shfl_xor_sync(0xffffffffu, m, o));
    if (lane == 0) rm[wid] = m;
    __syncthreads();
    float M = fmaxf(fmaxf(rm[0], rm[1]), fmaxf(rm[2], rm[3]));

    float e0 = __expf(sc0 - M), e1 = __expf(sc1 - M);
    float e2 = __expf(sc2 - M), e3 = __expf(sc3 - M);
    float ps = (e0 + e1) + (e2 + e3);
    #pragma unroll
    for (int o = 16; o > 0; o >>= 1) ps += __shfl_xor_sync(0xffffffffu, ps, o);
    if (lane == 0) rs[wid] = ps;
    __syncthreads();
    float inv = frcp((rs[0] + rs[1]) + (rs[2] + rs[3]));

    float p0 = e0 * inv, p1 = e1 * inv, p2 = e2 * inv, p3 = e3 * inv;
    float* ar = attn + row * SS;
    ar[tid]       = p0;
    ar[tid + 128] = p1;
    ar[tid + 256] = p2;
    ar[tid + 384] = p3;

    // --- attended = sum_j p_j * v_j ---
    const float4* vp = (const float4*)(g_v + (b * SS + tid) * 4);
    float4 vv0 = __ldg(vp);
    float4 vv1 = __ldg(vp + 128);
    float4 vv2 = __ldg(vp + 256);
    float4 vv3 = __ldg(vp + 384);
    float av[4];
    av[0] = p0 * vv0.x + p1 * vv1.x + p2 * vv2.x + p3 * vv3.x;
    av[1] = p0 * vv0.y + p1 * vv1.y + p2 * vv2.y + p3 * vv3.y;
    av[2] = p0 * vv0.z + p1 * vv1.z + p2 * vv2.z + p3 * vv3.z;
    av[3] = p0 * vv0.w + p1 * vv1.w + p2 * vv2.w + p3 * vv3.w;
    #pragma unroll
    for (int i = 0; i < 4; i++) {
        #pragma unroll
        for (int o = 16; o > 0; o >>= 1)
            av[i] += __shfl_xor_sync(0xffffffffu, av[i], o);
    }
    if (lane == 0) {
        #pragma unroll
        for (int i = 0; i < 4; i++) wsum[wid][i] = av[i];
    }
    __syncthreads();
    if (tid < 4) {
        att4[tid] = wsum[0][tid] + wsum[1][tid] + wsum[2][tid] + wsum[3][tid];
    }
    __syncthreads();

    // --- out = attended @ Wout + bout ---
    float w0 = att4[0], w1 = att4[1], w2 = att4[2], w3 = att4[3];
    float* orow = out + row * EE;
    #pragma unroll
    for (int r = 0; r < 4; r++) {
        int e = tid + r * 128;
        float o = __ldg(bout + e)
                + w0 * __ldg(Wout + e)
                + w1 * __ldg(Wout + EE + e)
                + w2 * __ldg(Wout + 2 * EE + e)
                + w3 * __ldg(Wout + 3 * EE + e);
        orow[e] = o;
    }
}

extern "C" void kernel_launch(void* const* d_in, const int* in_sizes, int n_in,
                              void* d_out, int out_size) {
    const float* x    = (const float*)d_in[0];
    const float* Wq   = (const float*)d_in[1];
    const float* bq   = (const float*)d_in[2];
    const float* Wk   = (const float*)d_in[3];
    const float* bk   = (const float*)d_in[4];
    const float* Wv   = (const float*)d_in[5];
    const float* bv   = (const float*)d_in[6];
    const float* qw   = (const float*)d_in[7];
    const float* Wout = (const float*)d_in[8];
    const float* bout = (const float*)d_in[9];
    float* out  = (float*)d_out;
    float* attn = out + (size_t)BB * SS * EE;

    qkv_setup_kernel<<<QKV_BLKS + 1, 128>>>(x, Wq, bq, Wk, bk, Wv, bv, qw);
    attn_kernel<<<NROWS, 128>>>(out, attn, Wout, bout);
}

// round 10
// speedup vs baseline: 1.1183x; 1.1183x over previous
#include <cuda_runtime.h>

#define NQ 4
#define QDIM 16
#define BB 4
#define SS 512
#define EE 512
#define NROWS (BB*SS)

// Scratch (no allocations allowed). g_q/g_k store tanh(tanh-projection).
__device__ __align__(16) float g_q[NROWS * 4];
__device__ __align__(16) float g_k[NROWS * 4];
__device__ __align__(16) float g_v[NROWS * 4];
__device__ float g_C[81];

struct c2 { float x, y; };
__device__ __forceinline__ c2 cmul(c2 a, c2 b) { return {a.x*b.x - a.y*b.y, a.x*b.y + a.y*b.x}; }
__device__ __forceinline__ c2 cadd(c2 a, c2 b) { return {a.x + b.x, a.y + b.y}; }

// ---- packed f32x2 helpers (FFMA2/FADD2/FMUL2: PTX-only) ----
typedef unsigned long long u64c;
__device__ __forceinline__ u64c pk2(float lo, float hi) {
    u64c r; asm("mov.b64 %0, {%1, %2};" : "=l"(r) : "f"(lo), "f"(hi)); return r;
}
__device__ __forceinline__ u64c pkc(float v) { return pk2(v, v); }
__device__ __forceinline__ void upk2(u64c v, float& lo, float& hi) {
    asm("mov.b64 {%0, %1}, %2;" : "=f"(lo), "=f"(hi) : "l"(v));
}
__device__ __forceinline__ u64c fma2(u64c a, u64c b, u64c c) {
    u64c d; asm("fma.rn.f32x2 %0, %1, %2, %3;" : "=l"(d) : "l"(a), "l"(b), "l"(c)); return d;
}
__device__ __forceinline__ u64c mul2(u64c a, u64c b) {
    u64c d; asm("mul.rn.f32x2 %0, %1, %2;" : "=l"(d) : "l"(a), "l"(b)); return d;
}
__device__ __forceinline__ u64c add2(u64c a, u64c b) {
    u64c d; asm("add.rn.f32x2 %0, %1, %2;" : "=l"(d) : "l"(a), "l"(b)); return d;
}
__device__ __forceinline__ float frcp(float x) {
    float r; asm("rcp.approx.f32 %0, %1;" : "=f"(r) : "f"(x)); return r;
}

// tanh(q + k) from tq = tanh(q), tk = tanh(k):  (tq+tk)/(1+tq*tk), packed.
__device__ __forceinline__ u64c tanh_sum2(u64c tq, u64c tk, u64c ONE) {
    u64c num = add2(tq, tk);
    u64c den = fma2(tq, tk, ONE);
    float d0, d1; upk2(den, d0, d1);
    return mul2(num, pk2(frcp(d0), frcp(d1)));
}

// Packed Taylor sin/cos, |a| < 0.965: err < 2e-8.
__device__ __forceinline__ void sincos2p(u64c a, u64c& s, u64c& c, u64c ONE) {
    u64c a2 = mul2(a, a);
    u64c h = fma2(a2, pkc(2.7557319e-6f), pkc(-1.9841270e-4f));
    h = fma2(a2, h, pkc(8.3333333e-3f));
    h = fma2(a2, h, pkc(-1.6666667e-1f));
    h = fma2(a2, h, ONE);
    s = mul2(a, h);
    u64c g = fma2(a2, pkc(-2.7557319e-7f), pkc(2.4801587e-5f));
    g = fma2(a2, g, pkc(-1.3888889e-3f));
    g = fma2(a2, g, pkc(4.1666667e-2f));
    g = fma2(a2, g, pkc(-0.5f));
    c = fma2(a2, g, ONE);
}

// Accurate tanh for the cold qkv path.
__device__ __forceinline__ float ftanh(float x) {
    float e2 = __expf(2.0f * x);
    return __fdividef(e2 - 1.0f, e2 + 1.0f);
}

// ---------------------------------------------------------------------------
// Setup body (128 threads): build U, A = Re(U^H Z U), collapse to 81-coeff C.
// Wire w <-> bit position (3 - w). Fast MUFU trig (gate angles ~0.05).
// ---------------------------------------------------------------------------
__device__ void setup_body(const float* __restrict__ qw, int tid) {
    __shared__ c2 G[8][4];
    __shared__ c2 U[QDIM][QDIM];
    __shared__ float A[QDIM][QDIM];

    if (tid < 8) {
        float a = qw[tid * 3 + 0] * 0.5f;
        float b = qw[tid * 3 + 1] * 0.5f;
        float c = qw[tid * 3 + 2] * 0.5f;
        float ca, sa, cb, sb, zc, zs;
        __sincosf(a, &sa, &ca);
        __sincosf(b, &sb, &cb);
        __sincosf(c, &zs, &zc);
        c2 X00 = {ca, 0.f}, X01 = {0.f, -sa}, X10 = {0.f, -sa}, X11 = {ca, 0.f};
        c2 M00 = {cb * X00.x - sb * X10.x, cb * X00.y - sb * X10.y};
        c2 M01 = {cb * X01.x - sb * X11.x, cb * X01.y - sb * X11.y};
        c2 M10 = {sb * X00.x + cb * X10.x, sb * X00.y + cb * X10.y};
        c2 M11 = {sb * X01.x + cb * X11.x, sb * X01.y + cb * X11.y};
        c2 e0 = {zc, -zs}, e1 = {zc, zs};
        G[tid][0] = cmul(e0, M00); G[tid][1] = cmul(e0, M01);
        G[tid][2] = cmul(e1, M10); G[tid][3] = cmul(e1, M11);
    }
    __syncthreads();

    if (tid < QDIM) {
        c2 amp[QDIM];
        #pragma unroll
        for (int d = 0; d < QDIM; d++) amp[d] = {0.f, 0.f};
        amp[tid] = {1.f, 0.f};
        #pragma unroll
        for (int layer = 0; layer < 2; layer++) {
            #pragma unroll
            for (int w = 0; w < 4; w++) {
                c2 g00 = G[layer * 4 + w][0], g01 = G[layer * 4 + w][1];
                c2 g10 = G[layer * 4 + w][2], g11 = G[layer * 4 + w][3];
                int mask = 1 << (3 - w);
                #pragma unroll
                for (int d = 0; d < QDIM; d++) {
                    if (d & mask) continue;
                    c2 x0 = amp[d], x1 = amp[d | mask];
                    amp[d]        = cadd(cmul(g00, x0), cmul(g01, x1));
                    amp[d | mask] = cadd(cmul(g10, x0), cmul(g11, x1));
                }
            }
            const int cm[4] = {8, 4, 2, 1};
            const int tm[4] = {4, 2, 1, 8};
            #pragma unroll
            for (int p = 0; p < 4; p++) {
                #pragma unroll
                for (int d = 0; d < QDIM; d++) {
                    if ((d & cm[p]) && !(d & tm[p])) {
                        c2 t = amp[d];
                        amp[d] = amp[d | tm[p]];
                        amp[d | tm[p]] = t;
                    }
                }
            }
        }
        #pragma unroll
        for (int m = 0; m < QDIM; m++) U[m][tid] = amp[m];
    }
    __syncthreads();

    #pragma unroll
    for (int it = 0; it < 2; it++) {
        int idx = tid + it * 128;
        int d = idx >> 4, e = idx & 15;
        float s = 0.f;
        #pragma unroll
        for (int m = 0; m < QDIM; m++) {
            float z = 4.0f - 2.0f * (float)__popc(m);
            s += z * (U[m][d].x * U[m][e].x + U[m][d].y * U[m][e].y);
        }
        A[d][e] = s;
    }
    __syncthreads();

    if (tid < 81) {
        int t0 = tid / 27, t1 = (tid / 9) % 3, t2 = (tid / 3) % 3, t3 = tid % 3;
        int tw[4] = {t0, t1, t2, t3};
        int xmask = 0, m1 = 0;
        #pragma unroll
        for (int w = 0; w < 4; w++) {
            if (tw[w] == 2) xmask |= 1 << (3 - w);
            if (tw[w] == 1) m1   |= 1 << (3 - w);
        }
        float s = 0.f;
        #pragma unroll
        for (int d = 0; d < QDIM; d++) {
            float sgn = (__popc(d & m1) & 1) ? -1.0f : 1.0f;
            s += sgn * A[d][d ^ xmask];
        }
        g_C[tid] = s * 0.0625f;
    }
}

// ---------------------------------------------------------------------------
// Merged setup + QKV (R7 benched-best form). Block 0: setup. Blocks
// 1..NROWS: one (b,s) row each, strided loop.
// Stores tq = tanh(tanh(xWq+bq)), tk = tanh(tanh(xWk+bk)), v = xWv+bv.
// ---------------------------------------------------------------------------
__global__ void __launch_bounds__(128) qkv_setup_kernel(
        const float* __restrict__ x,
        const float* __restrict__ Wq, const float* __restrict__ bq,
        const float* __restrict__ Wk, const float* __restrict__ bk,
        const float* __restrict__ Wv, const float* __restrict__ bv,
        const float* __restrict__ qw) {
    int tid = threadIdx.x;  // 128
    if (blockIdx.x == 0) { setup_body(qw, tid); return; }

    int row = blockIdx.x - 1;
    const float* xr = x + row * EE;

    float acc[12];
    #pragma unroll
    for (int i = 0; i < 12; i++) acc[i] = 0.f;

    #pragma unroll 2
    for (int e = tid; e < EE; e += 128) {
        float xv = __ldg(xr + e);
        float4 wq = __ldg((const float4*)(Wq + e * 4));
        float4 wk = __ldg((const float4*)(Wk + e * 4));
        float4 wv = __ldg((const float4*)(Wv + e * 4));
        acc[0] += xv * wq.x; acc[1] += xv * wq.y; acc[2]  += xv * wq.z; acc[3]  += xv * wq.w;
        acc[4] += xv * wk.x; acc[5] += xv * wk.y; acc[6]  += xv * wk.z; acc[7]  += xv * wk.w;
        acc[8] += xv * wv.x; acc[9] += xv * wv.y; acc[10] += xv * wv.z; acc[11] += xv * wv.w;
    }
    #pragma unroll
    for (int i = 0; i < 12; i++) {
        #pragma unroll
        for (int o = 16; o > 0; o >>= 1)
            acc[i] += __shfl_xor_sync(0xffffffffu, acc[i], o);
    }
    __shared__ float wr[4][12];
    int wid = tid >> 5, lane = tid & 31;
    if (lane == 0) {
        #pragma unroll
        for (int i = 0; i < 12; i++) wr[wid][i] = acc[i];
    }
    __syncthreads();
    if (tid < 12) {
        float s = wr[0][tid] + wr[1][tid] + wr[2][tid] + wr[3][tid];
        if (tid < 4) {
            g_q[row * 4 + tid] = ftanh(ftanh(s + bq[tid]));
        } else if (tid < 8) {
            g_k[row * 4 + (tid - 4)] = ftanh(ftanh(s + bk[tid - 4]));
        } else {
            g_v[row * 4 + (tid - 8)] = s + bv[tid - 8];
        }
    }
}

// ---------------------------------------------------------------------------
// Fused scores + softmax + attended + output. One block (128 thr) per (b,i).
// Thread t owns j = {t, t+128, t+256, t+384}: two packed FFMA2 chains.
// Short critical path: NO max-reduction (|score| <= 2, exp cannot overflow),
// one fused 5-way block reduction (ps, e*v[0..3]), att computed redundantly
// per-thread. Only 2 barriers per block.
// ---------------------------------------------------------------------------
__global__ void __launch_bounds__(128) attn_kernel(
        float* __restrict__ out, float* __restrict__ attn,
        const float* __restrict__ Wout, const float* __restrict__ bout) {
    int row = blockIdx.x;
    int tid = threadIdx.x;  // 128
    int b = row >> 9;       // row / SS
    int wid = tid >> 5, lane = tid & 31;

    __shared__ __align__(8) float2 Csh2[81];
    __shared__ float qsh[4];
    __shared__ float wsum[4][5];   // per-warp partials: ps, ev0..ev3

    if (tid < 81) { float c = g_C[tid]; Csh2[tid] = make_float2(c, c); }
    if (tid < 4)  qsh[tid] = g_q[row * 4 + tid];

    // 8 independent LDG.128 in flight from the start.
    const float4* kp = (const float4*)(g_k + (b * SS + tid) * 4);
    const float4* vp = (const float4*)(g_v + (b * SS + tid) * 4);
    float4 kk0 = __ldg(kp);
    float4 kk1 = __ldg(kp + 128);
    float4 kk2 = __ldg(kp + 256);
    float4 kk3 = __ldg(kp + 384);
    float4 vv0 = __ldg(vp);
    float4 vv1 = __ldg(vp + 128);
    float4 vv2 = __ldg(vp + 256);
    float4 vv3 = __ldg(vp + 384);
    __syncthreads();

    const u64c ONE = pkc(1.0f);
    u64c tq0 = pkc(qsh[0]), tq1 = pkc(qsh[1]), tq2 = pkc(qsh[2]), tq3 = pkc(qsh[3]);

    // chain A = (j, j+128), chain B = (j+256, j+384)
    u64c a0A = tanh_sum2(tq0, pk2(kk0.x, kk1.x), ONE);
    u64c a1A = tanh_sum2(tq1, pk2(kk0.y, kk1.y), ONE);
    u64c a2A = tanh_sum2(tq2, pk2(kk0.z, kk1.z), ONE);
    u64c a3A = tanh_sum2(tq3, pk2(kk0.w, kk1.w), ONE);
    u64c a0B = tanh_sum2(tq0, pk2(kk2.x, kk3.x), ONE);
    u64c a1B = tanh_sum2(tq1, pk2(kk2.y, kk3.y), ONE);
    u64c a2B = tanh_sum2(tq2, pk2(kk2.z, kk3.z), ONE);
    u64c a3B = tanh_sum2(tq3, pk2(kk2.w, kk3.w), ONE);

    u64c c0A, s0A, c1A, s1A, c2A, s2A, c3A, s3A;
    u64c c0B, s0B, c1B, s1B, c2B, s2B, c3B, s3B;
    sincos2p(a0A, s0A, c0A, ONE); sincos2p(a1A, s1A, c1A, ONE);
    sincos2p(a2A, s2A, c2A, ONE); sincos2p(a3A, s3A, c3A, ONE);
    sincos2p(a0B, s0B, c0B, ONE); sincos2p(a1B, s1B, c1B, ONE);
    sincos2p(a2B, s2B, c2B, ONE); sincos2p(a3B, s3B, c3B, ONE);

    // contraction: both chains share each coefficient LDS.64.
    const u64c* Cd = (const u64c*)Csh2;
    u64c B0A[3], B0B[3];
    #pragma unroll
    for (int t0 = 0; t0 < 3; t0++) {
        u64c B1A[3], B1B[3];
        #pragma unroll
        for (int t1 = 0; t1 < 3; t1++) {
            int base = (t0 * 3 + t1) * 9;
            u64c C0 = Cd[base + 0], C1 = Cd[base + 1], C2 = Cd[base + 2];
            u64c C3 = Cd[base + 3], C4 = Cd[base + 4], C5 = Cd[base + 5];
            u64c C6 = Cd[base + 6], C7 = Cd[base + 7], C8 = Cd[base + 8];
            u64c A20 = fma2(C2, s3A, fma2(C1, c3A, C0));
            u64c A21 = fma2(C5, s3A, fma2(C4, c3A, C3));
            u64c A22 = fma2(C8, s3A, fma2(C7, c3A, C6));
            B1A[t1] = fma2(A22, s2A, fma2(A21, c2A, A20));
            u64c D20 = fma2(C2, s3B, fma2(C1, c3B, C0));
            u64c D21 = fma2(C5, s3B, fma2(C4, c3B, C3));
            u64c D22 = fma2(C8, s3B, fma2(C7, c3B, C6));
            B1B[t1] = fma2(D22, s2B, fma2(D21, c2B, D20));
        }
        B0A[t0] = fma2(B1A[2], s1A, fma2(B1A[1], c1A, B1A[0]));
        B0B[t0] = fma2(B1B[2], s1B, fma2(B1B[1], c1B, B1B[0]));
    }
    u64c totA = fma2(B0A[2], s0A, fma2(B0A[1], c0A, B0A[0]));
    u64c totB = fma2(B0B[2], s0B, fma2(B0B[1], c0B, B0B[0]));

    float sc0, sc1, sc2, sc3;
    upk2(totA, sc0, sc1);
    upk2(totB, sc2, sc3);

    // exp without max: |score/2| <= 2, exp in [0.135, 7.39] — safe.
    float e0 = __expf(0.5f * sc0);
    float e1 = __expf(0.5f * sc1);
    float e2 = __expf(0.5f * sc2);
    float e3 = __expf(0.5f * sc3);

    // fused 5-way reduction: ps and e-weighted v sums.
    float ps  = (e0 + e1) + (e2 + e3);
    float ev0 = e0 * vv0.x + e1 * vv1.x + e2 * vv2.x + e3 * vv3.x;
    float ev1 = e0 * vv0.y + e1 * vv1.y + e2 * vv2.y + e3 * vv3.y;
    float ev2 = e0 * vv0.z + e1 * vv1.z + e2 * vv2.z + e3 * vv3.z;
    float ev3 = e0 * vv0.w + e1 * vv1.w + e2 * vv2.w + e3 * vv3.w;
    #pragma unroll
    for (int o = 16; o > 0; o >>= 1) {
        ps  += __shfl_xor_sync(0xffffffffu, ps,  o);
        ev0 += __shfl_xor_sync(0xffffffffu, ev0, o);
        ev1 += __shfl_xor_sync(0xffffffffu, ev1, o);
        ev2 += __shfl_xor_sync(0xffffffffu, ev2, o);
        ev3 += __shfl_xor_sync(0xffffffffu, ev3, o);
    }
    if (lane == 0) {
        wsum[wid][0] = ps;
        wsum[wid][1] = ev0; wsum[wid][2] = ev1;
        wsum[wid][3] = ev2; wsum[wid][4] = ev3;
    }
    __syncthreads();

    float pst = (wsum[0][0] + wsum[1][0]) + (wsum[2][0] + wsum[3][0]);
    float inv = frcp(pst);
    float at0 = ((wsum[0][1] + wsum[1][1]) + (wsum[2][1] + wsum[3][1])) * inv;
    float at1 = ((wsum[0][2] + wsum[1][2]) + (wsum[2][2] + wsum[3][2])) * inv;
    float at2 = ((wsum[0][3] + wsum[1][3]) + (wsum[2][3] + wsum[3][3])) * inv;
    float at3 = ((wsum[0][4] + wsum[1][4]) + (wsum[2][4] + wsum[3][4])) * inv;

    // attention probabilities
    float* ar = attn + row * SS;
    ar[tid]       = e0 * inv;
    ar[tid + 128] = e1 * inv;
    ar[tid + 256] = e2 * inv;
    ar[tid + 384] = e3 * inv;

    // --- out = attended @ Wout + bout ---
    float* orow = out + row * EE;
    #pragma unroll
    for (int r = 0; r < 4; r++) {
        int e = tid + r * 128;
        float o = __ldg(bout + e)
                + at0 * __ldg(Wout + e)
                + at1 * __ldg(Wout + EE + e)
                + at2 * __ldg(Wout + 2 * EE + e)
                + at3 * __ldg(Wout + 3 * EE + e);
        orow[e] = o;
    }
}

extern "C" void kernel_launch(void* const* d_in, const int* in_sizes, int n_in,
                              void* d_out, int out_size) {
    const float* x    = (const float*)d_in[0];
    const float* Wq   = (const float*)d_in[1];
    const float* bq   = (const float*)d_in[2];
    const float* Wk   = (const float*)d_in[3];
    const float* bk   = (const float*)d_in[4];
    const float* Wv   = (const float*)d_in[5];
    const float* bv   = (const float*)d_in[6];
    const float* qw   = (const float*)d_in[7];
    const float* Wout = (const float*)d_in[8];
    const float* bout = (const float*)d_in[9];
    float* out  = (float*)d_out;
    float* attn = out + (size_t)BB * SS * EE;

    qkv_setup_kernel<<<NROWS + 1, 128>>>(x, Wq, bq, Wk, bk, Wv, bv, qw);
    attn_kernel<<<NROWS, 128>>>(out, attn, Wout, bout);
}